// round 3
// baseline (speedup 1.0000x reference)
#include <cuda_runtime.h>
#include <cuda_bf16.h>

// out[t, :] = W[x[t], :] + b   for t in [0, 8192), D = 2048
// x: int32 [8192], W: f32 [50257, 2048], b: f32 [2048]
// HBM-latency bound previously (MLP_p1=2). Now: 4 tokens per CTA,
// 8 independent float4 W-loads per thread, bias amortized 4x.

#define D_MODEL 2048
#define D4      (D_MODEL / 4)   // 512 float4 per row
#define TOKENS  8192
#define TPC     4               // tokens per CTA

__global__ __launch_bounds__(256)
void embed_gather_kernel(const int* __restrict__ x,
                         const float4* __restrict__ W4,
                         const float4* __restrict__ b4,
                         float4* __restrict__ out4) {
    const int t0 = blockIdx.x * TPC;

    // 4 independent index loads
    const long long r0 = (long long)x[t0 + 0];
    const long long r1 = (long long)x[t0 + 1];
    const long long r2 = (long long)x[t0 + 2];
    const long long r3 = (long long)x[t0 + 3];

    const int c0 = threadIdx.x;
    const int c1 = threadIdx.x + 256;

    // bias loaded once, reused for all 4 tokens (L1-resident anyway)
    const float4 bb0 = b4[c0];
    const float4 bb1 = b4[c1];

    // 8 independent gathers — front-batched for max MLP
    float4 v00 = __ldg(W4 + r0 * D4 + c0);
    float4 v01 = __ldg(W4 + r0 * D4 + c1);
    float4 v10 = __ldg(W4 + r1 * D4 + c0);
    float4 v11 = __ldg(W4 + r1 * D4 + c1);
    float4 v20 = __ldg(W4 + r2 * D4 + c0);
    float4 v21 = __ldg(W4 + r2 * D4 + c1);
    float4 v30 = __ldg(W4 + r3 * D4 + c0);
    float4 v31 = __ldg(W4 + r3 * D4 + c1);

    v00.x += bb0.x; v00.y += bb0.y; v00.z += bb0.z; v00.w += bb0.w;
    v01.x += bb1.x; v01.y += bb1.y; v01.z += bb1.z; v01.w += bb1.w;
    v10.x += bb0.x; v10.y += bb0.y; v10.z += bb0.z; v10.w += bb0.w;
    v11.x += bb1.x; v11.y += bb1.y; v11.z += bb1.z; v11.w += bb1.w;
    v20.x += bb0.x; v20.y += bb0.y; v20.z += bb0.z; v20.w += bb0.w;
    v21.x += bb1.x; v21.y += bb1.y; v21.z += bb1.z; v21.w += bb1.w;
    v30.x += bb0.x; v30.y += bb0.y; v30.z += bb0.z; v30.w += bb0.w;
    v31.x += bb1.x; v31.y += bb1.y; v31.z += bb1.z; v31.w += bb1.w;

    float4* __restrict__ dst = out4 + (long long)t0 * D4;
    dst[0 * D4 + c0] = v00;
    dst[0 * D4 + c1] = v01;
    dst[1 * D4 + c0] = v10;
    dst[1 * D4 + c1] = v11;
    dst[2 * D4 + c0] = v20;
    dst[2 * D4 + c1] = v21;
    dst[3 * D4 + c0] = v30;
    dst[3 * D4 + c1] = v31;
}

extern "C" void kernel_launch(void* const* d_in, const int* in_sizes, int n_in,
                              void* d_out, int out_size) {
    const int*    x = (const int*)d_in[0];        // [4, 2048] int32
    const float4* W = (const float4*)d_in[1];     // [50257, 2048] f32
    const float4* b = (const float4*)d_in[2];     // [2048] f32
    float4* out = (float4*)d_out;                 // [4, 2048, 2048] f32

    embed_gather_kernel<<<TOKENS / TPC, 256>>>(x, W, b, out);
}